// round 6
// baseline (speedup 1.0000x reference)
#include <cuda_runtime.h>
#include <cuda_fp16.h>
#include <mma.h>
using namespace nvcuda;

#define NN 100000
#define NNP 100032          // padded to 64-node k2 blocks
#define NE 1600000

// fp16 copies of x and W for tensor-core k2
__device__ __half g_xh[(size_t)NNP * 32];
__device__ __half g_wh[25 * 32 * 32];
// xw in fp16: [NNP][25 kernels][32 feats] = 1600B/node
__device__ uint2 g_xwh[(size_t)NNP * 200];
__device__ float g_q[(size_t)NNP * 25];      // q[n][k] = xw[n][k,:] . att2
__device__ float g_ex[NE];                   // per-edge exp(alpha)
__device__ float g_acc[(size_t)NN * 32];
__device__ float g_xrb[(size_t)NN * 32];
__device__ float g_rdot[NN];
__device__ float g_denom[NN];

typedef unsigned long long u64;

__device__ __forceinline__ u64 pack2(float a, float b) {
    u64 r; asm("mov.b64 %0,{%1,%2};" : "=l"(r) : "f"(a), "f"(b)); return r;
}
__device__ __forceinline__ void unpack2(u64 v, float& a, float& b) {
    asm("mov.b64 {%0,%1},%2;" : "=f"(a), "=f"(b) : "l"(v));
}
__device__ __forceinline__ u64 fma2(u64 a, u64 b, u64 c) {
    u64 d; asm("fma.rn.f32x2 %0,%1,%2,%3;" : "=l"(d) : "l"(a), "l"(b), "l"(c)); return d;
}
__device__ __forceinline__ unsigned h2b(float a, float b) {
    unsigned r; asm("cvt.rn.f16x2.f32 %0,%2,%1;" : "=r"(r) : "f"(a), "f"(b));
    return r;   // low half = a
}

// ---------------------------------------------------------------------------
// K0: convert W to fp16 + zero q
// ---------------------------------------------------------------------------
__global__ __launch_bounds__(256) void k0_prep(const float* __restrict__ W)
{
    int i = blockIdx.x * 256 + threadIdx.x;
    if (i < 12800) {                         // 12800 half2 slots of W
        float2 v = ((const float2*)W)[i];
        ((unsigned*)g_wh)[i] = h2b(v.x, v.y);
    }
    if (i < (NNP * 25) / 4)                  // 625200 float4 slots of q
        ((float4*)g_q)[i] = make_float4(0.f, 0.f, 0.f, 0.f);
}

// ---------------------------------------------------------------------------
// K1: root transform + attention dot + zero-init + x->fp16 copy
// ---------------------------------------------------------------------------
__global__ __launch_bounds__(256) void k1_node(
    const float* __restrict__ x, const float* __restrict__ rootW,
    const float* __restrict__ attW, const float* __restrict__ bias)
{
    __shared__ __align__(16) float Rs[1024];
    __shared__ float a1s[32], bsh[32];
    int tid = threadIdx.x;
    ((float4*)Rs)[tid] = ((const float4*)rootW)[tid];
    if (tid < 32) { a1s[tid] = attW[tid]; bsh[tid] = bias[tid]; }
    __syncthreads();

    int n = blockIdx.x * 256 + tid;
    if (n >= NN) return;

    float xv[32];
    const float4* xp = (const float4*)(x + (size_t)n * 32);
#pragma unroll
    for (int j = 0; j < 8; j++) {
        float4 t = xp[j];
        xv[4*j] = t.x; xv[4*j+1] = t.y; xv[4*j+2] = t.z; xv[4*j+3] = t.w;
    }
    uint4* xhp = ((uint4*)g_xh) + (size_t)n * 4;
#pragma unroll
    for (int j = 0; j < 4; j++) {
        uint4 h;
        h.x = h2b(xv[8*j],   xv[8*j+1]);
        h.y = h2b(xv[8*j+2], xv[8*j+3]);
        h.z = h2b(xv[8*j+4], xv[8*j+5]);
        h.w = h2b(xv[8*j+6], xv[8*j+7]);
        xhp[j] = h;
    }

    u64 acc[16];
#pragma unroll
    for (int m = 0; m < 16; m++) acc[m] = pack2(0.f, 0.f);
#pragma unroll
    for (int f = 0; f < 32; f++) {
        u64 xf = pack2(xv[f], xv[f]);
        const ulonglong2* rp = (const ulonglong2*)(Rs + f * 32);
#pragma unroll
        for (int j = 0; j < 8; j++) {
            ulonglong2 w = rp[j];
            acc[2*j]   = fma2(xf, w.x, acc[2*j]);
            acc[2*j+1] = fma2(xf, w.y, acc[2*j+1]);
        }
    }
    float xr[32];
#pragma unroll
    for (int m = 0; m < 16; m++) unpack2(acc[m], xr[2*m], xr[2*m+1]);

    float rd = 0.f;
#pragma unroll
    for (int o = 0; o < 32; o++) rd += xr[o] * a1s[o];
    g_rdot[n]  = rd;
    g_denom[n] = 0.f;

    float4* xrbp = (float4*)(g_xrb + (size_t)n * 32);
    float4* accp = (float4*)(g_acc + (size_t)n * 32);
#pragma unroll
    for (int j = 0; j < 8; j++) {
        float4 v;
        v.x = xr[4*j]   + bsh[4*j];
        v.y = xr[4*j+1] + bsh[4*j+1];
        v.z = xr[4*j+2] + bsh[4*j+2];
        v.w = xr[4*j+3] + bsh[4*j+3];
        xrbp[j] = v;
        accp[j] = make_float4(0.f, 0.f, 0.f, 0.f);
    }
}

// ---------------------------------------------------------------------------
// K2: tensor-core xw + q epilogue. W staged in smem (LDSM path).
//   8 warps/block, 64 nodes/block; warp (mtile=w&3, ntile=w>>2).
// ---------------------------------------------------------------------------
__global__ __launch_bounds__(256) void k2_wmma(const float* __restrict__ attW)
{
    extern __shared__ __align__(16) char smraw[];
    __half* Wsm = (__half*)smraw;               // 51200 B
    float* stag = (float*)(smraw + 51200);      // 8192 B

    int tid = threadIdx.x;
    // stage all 25 W_k (fp16) into smem: 3200 uint4
    {
        const uint4* wsrc = (const uint4*)g_wh;
        uint4* wdst = (uint4*)Wsm;
#pragma unroll
        for (int i = 0; i < 13; i++) {
            int idx = tid + 256 * i;
            if (idx < 3200) wdst[idx] = wsrc[idx];
        }
    }
    __syncthreads();

    int warp = tid >> 5, lane = tid & 31;
    int mtile = warp & 3, ntile = warp >> 2;
    int m0 = blockIdx.x * 64 + mtile * 16;

    wmma::fragment<wmma::matrix_a, 16, 16, 16, __half, wmma::row_major> a0, a1;
    wmma::load_matrix_sync(a0, g_xh + (size_t)m0 * 32,      32);
    wmma::load_matrix_sync(a1, g_xh + (size_t)m0 * 32 + 16, 32);

    float* sw = stag + warp * 256;
    int r = lane >> 1, h = lane & 1;
    const float* sp = sw + r * 16 + h * 8;
    uint4* outp = ((uint4*)g_xwh) + (size_t)(m0 + r) * 100 + ntile * 2 + h;
    // att2 slice for this lane's 8 feats
    float4 at0 = __ldg(((const float4*)(attW + 32)) + ntile * 4 + h * 2);
    float4 at1 = __ldg(((const float4*)(attW + 32)) + ntile * 4 + h * 2 + 1);
    float* qp = g_q + (size_t)(m0 + r) * 25;

#pragma unroll 1
    for (int k = 0; k < 25; k++) {
        wmma::fragment<wmma::matrix_b, 16, 16, 16, __half, wmma::row_major> b;
        wmma::fragment<wmma::accumulator, 16, 16, 16, float> c;
        wmma::fill_fragment(c, 0.f);
        wmma::load_matrix_sync(b, Wsm + k * 1024 + ntile * 16, 32);
        wmma::mma_sync(c, a0, b, c);
        wmma::load_matrix_sync(b, Wsm + k * 1024 + 512 + ntile * 16, 32);
        wmma::mma_sync(c, a1, b, c);
        wmma::store_matrix_sync(sw, c, 16, wmma::mem_row_major);
        __syncwarp();
        float s0 = sp[0], s1 = sp[1], s2 = sp[2], s3 = sp[3];
        float s4 = sp[4], s5 = sp[5], s6 = sp[6], s7 = sp[7];
        uint4 v;
        v.x = h2b(s0, s1); v.y = h2b(s2, s3);
        v.z = h2b(s4, s5); v.w = h2b(s6, s7);
        outp[k * 4] = v;
        // q partial: dot of this lane's 8 feats with att2 slice
        float qd = s0*at0.x + s1*at0.y + s2*at0.z + s3*at0.w
                 + s4*at1.x + s5*at1.y + s6*at1.z + s7*at1.w;
        qd += __shfl_xor_sync(0xffffffffu, qd, 1);   // combine h halves
        if (h == 0) atomicAdd(qp + k, qd);           // 2 adds (ntile 0/1)
        __syncwarp();
    }
}

// ---------------------------------------------------------------------------
// KALPHA: per-edge attention logits from q; store ex, accumulate denom.
// ---------------------------------------------------------------------------
__global__ __launch_bounds__(256) void kalpha(
    const int* __restrict__ ei, const float* __restrict__ pseudo)
{
    int e = blockIdx.x * 256 + threadIdx.x;     // NE = 6250 * 256 exact
    int row = __ldg(ei + e);
    int col = __ldg(ei + NE + e);
    float2 pr = __ldg(((const float2*)pseudo) + e);
    float p0 = pr.x * 4.f, p1 = pr.y * 4.f;
    float fl0 = floorf(p0), fl1 = floorf(p1);
    float fr0 = p0 - fl0,   fr1 = p1 - fl1;
    int i0 = (int)fl0, i1 = (int)fl1;

    const float* qb = g_q + (size_t)col * 25 + (i0 + 5 * i1);
    float q0 = __ldg(qb),     q1 = __ldg(qb + 1);
    float q5 = __ldg(qb + 5), q6 = __ldg(qb + 6);
    float g0 = 1.f - fr0, g1 = 1.f - fr1;
    float am = g0*g1*q0 + fr0*g1*q1 + g0*fr1*q5 + fr0*fr1*q6;

    float alpha = am + __ldg(g_rdot + row);
    alpha = (alpha > 0.f) ? alpha : 0.2f * alpha;       // leaky relu
    float ex = __expf(alpha);       // softmax max-shift cancels in the ratio
    g_ex[e] = ex;
    atomicAdd(g_denom + row, ex);
}

// ---------------------------------------------------------------------------
// K3: slim gather+reduce. 8 lanes/edge; ex folded into basis weights.
// ---------------------------------------------------------------------------
__global__ __launch_bounds__(256) void k3_edge(
    const int* __restrict__ ei, const float* __restrict__ pseudo)
{
    int t = blockIdx.x * 256 + threadIdx.x;
    int e   = t >> 3;
    int sub = t & 7;

    int row = __ldg(ei + e);
    int col = __ldg(ei + NE + e);
    float ex = __ldg(g_ex + e);
    float2 pr = __ldg(((const float2*)pseudo) + e);
    float p0 = pr.x * 4.f, p1 = pr.y * 4.f;
    float fl0 = floorf(p0), fl1 = floorf(p1);
    float fr0 = p0 - fl0,   fr1 = p1 - fl1;
    int i0 = (int)fl0, i1 = (int)fl1;
    int w0 = i0 + 5 * i1;

    float g0 = 1.f - fr0, g1 = 1.f - fr1;
    float b00 = g0*g1*ex,  b10 = fr0*g1*ex;
    float b01 = g0*fr1*ex, b11 = fr0*fr1*ex;

    const uint2* base = g_xwh + (size_t)col * 200 + sub;
    uint2 v0 = __ldg(base + w0 * 8);
    uint2 v1 = __ldg(base + (w0 + 1) * 8);
    uint2 v2 = __ldg(base + (w0 + 5) * 8);
    uint2 v3 = __ldg(base + (w0 + 6) * 8);

    float m0, m1, m2, m3;
    {
        float2 f0 = __half22float2(*reinterpret_cast<const __half2*>(&v0.x));
        float2 f1 = __half22float2(*reinterpret_cast<const __half2*>(&v0.y));
        m0 = b00 * f0.x; m1 = b00 * f0.y; m2 = b00 * f1.x; m3 = b00 * f1.y;
    }
    {
        float2 f0 = __half22float2(*reinterpret_cast<const __half2*>(&v1.x));
        float2 f1 = __half22float2(*reinterpret_cast<const __half2*>(&v1.y));
        m0 = fmaf(b10, f0.x, m0); m1 = fmaf(b10, f0.y, m1);
        m2 = fmaf(b10, f1.x, m2); m3 = fmaf(b10, f1.y, m3);
    }
    {
        float2 f0 = __half22float2(*reinterpret_cast<const __half2*>(&v2.x));
        float2 f1 = __half22float2(*reinterpret_cast<const __half2*>(&v2.y));
        m0 = fmaf(b01, f0.x, m0); m1 = fmaf(b01, f0.y, m1);
        m2 = fmaf(b01, f1.x, m2); m3 = fmaf(b01, f1.y, m3);
    }
    {
        float2 f0 = __half22float2(*reinterpret_cast<const __half2*>(&v3.x));
        float2 f1 = __half22float2(*reinterpret_cast<const __half2*>(&v3.y));
        m0 = fmaf(b11, f0.x, m0); m1 = fmaf(b11, f0.y, m1);
        m2 = fmaf(b11, f1.x, m2); m3 = fmaf(b11, f1.y, m3);
    }

    float* ap = g_acc + (size_t)row * 32 + sub * 4;
    asm volatile("red.global.add.v4.f32 [%0], {%1,%2,%3,%4};"
                 :: "l"(ap), "f"(m0), "f"(m1), "f"(m2), "f"(m3)
                 : "memory");
}

// ---------------------------------------------------------------------------
// K4: out = acc / (denom + 1e-16) + (x_root + bias)
// ---------------------------------------------------------------------------
__global__ __launch_bounds__(256) void k4_out(float* __restrict__ out)
{
    int i = blockIdx.x * 256 + threadIdx.x;
    int n = i >> 3;
    float r = 1.f / (g_denom[n] + 1e-16f);
    float4 a  = ((const float4*)g_acc)[i];
    float4 xr = ((const float4*)g_xrb)[i];
    float4 o;
    o.x = fmaf(a.x, r, xr.x);
    o.y = fmaf(a.y, r, xr.y);
    o.z = fmaf(a.z, r, xr.z);
    o.w = fmaf(a.w, r, xr.w);
    ((float4*)out)[i] = o;
}

extern "C" void kernel_launch(void* const* d_in, const int* in_sizes, int n_in,
                              void* d_out, int out_size)
{
    const float* x      = (const float*)d_in[0];
    const int*   ei     = (const int*)d_in[1];
    const float* pseudo = (const float*)d_in[2];
    const float* W      = (const float*)d_in[3];
    const float* rootW  = (const float*)d_in[4];
    const float* attW   = (const float*)d_in[5];
    const float* bias   = (const float*)d_in[6];
    float* out = (float*)d_out;

    static bool attr_set = false;
    if (!attr_set) {
        cudaFuncSetAttribute(k2_wmma,
            cudaFuncAttributeMaxDynamicSharedMemorySize, 59392);
        attr_set = true;
    }

    k0_prep<<<(NNP * 25 / 4 + 255) / 256, 256>>>(W);
    k1_node<<<(NN + 255) / 256, 256>>>(x, rootW, attW, bias);
    k2_wmma<<<NNP / 64, 256, 59392>>>(attW);
    kalpha <<<NE / 256, 256>>>(ei, pseudo);
    k3_edge<<<(NE * 8) / 256, 256>>>(ei, pseudo);
    k4_out <<<(NN * 32 / 4) / 256, 256>>>(out);
}

// round 7
// speedup vs baseline: 1.5551x; 1.5551x over previous
#include <cuda_runtime.h>
#include <cuda_fp16.h>

#define NN 100000
#define NNP 100096          // padded to 128-node k2 blocks (782 * 128)
#define NE 1600000

// fp16 copies of x and W
__device__ __half g_xh[(size_t)NNP * 32];
__device__ __half g_wh[25 * 32 * 32];
// xw' (PERMUTED feature layout) fp16: [NNP][25 kernels][64B]
__device__ uint2 g_xwp[(size_t)NNP * 200];
__device__ float g_att2p[32];                // attW[32..] permuted to xw' layout
__device__ float g_acc[(size_t)NN * 32];     // permuted space
__device__ float g_xrb[(size_t)NN * 32];     // canonical
__device__ float g_rdot[NN];
__device__ float g_denom[NN];

typedef unsigned long long u64;

__device__ __forceinline__ u64 pack2(float a, float b) {
    u64 r; asm("mov.b64 %0,{%1,%2};" : "=l"(r) : "f"(a), "f"(b)); return r;
}
__device__ __forceinline__ void unpack2(u64 v, float& a, float& b) {
    asm("mov.b64 {%0,%1},%2;" : "=f"(a), "=f"(b) : "l"(v));
}
__device__ __forceinline__ u64 fma2(u64 a, u64 b, u64 c) {
    u64 d; asm("fma.rn.f32x2 %0,%1,%2,%3;" : "=l"(d) : "l"(a), "l"(b), "l"(c)); return d;
}
__device__ __forceinline__ unsigned h2b(float a, float b) {
    unsigned r; asm("cvt.rn.f16x2.f32 %0,%2,%1;" : "=r"(r) : "f"(a), "f"(b));
    return r;   // low half = a
}
__device__ __forceinline__ unsigned sm_u32(const void* p) {
    unsigned r;
    asm("{.reg .u64 t; cvta.to.shared.u64 t, %1; cvt.u32.u64 %0, t;}"
        : "=r"(r) : "l"(p));
    return r;
}
__device__ __forceinline__ void ldsm4(unsigned& r0, unsigned& r1,
                                      unsigned& r2, unsigned& r3, unsigned a) {
    asm volatile("ldmatrix.sync.aligned.m8n8.x4.shared.b16 {%0,%1,%2,%3}, [%4];"
                 : "=r"(r0), "=r"(r1), "=r"(r2), "=r"(r3) : "r"(a));
}
__device__ __forceinline__ void ldsm4t(unsigned& r0, unsigned& r1,
                                       unsigned& r2, unsigned& r3, unsigned a) {
    asm volatile("ldmatrix.sync.aligned.m8n8.x4.trans.shared.b16 {%0,%1,%2,%3}, [%4];"
                 : "=r"(r0), "=r"(r1), "=r"(r2), "=r"(r3) : "r"(a));
}
__device__ __forceinline__ void mma16816(float* c, const unsigned* a,
                                         unsigned b0, unsigned b1) {
    asm volatile("mma.sync.aligned.m16n8k16.row.col.f32.f16.f16.f32 "
                 "{%0,%1,%2,%3}, {%4,%5,%6,%7}, {%8,%9}, {%0,%1,%2,%3};"
                 : "+f"(c[0]), "+f"(c[1]), "+f"(c[2]), "+f"(c[3])
                 : "r"(a[0]), "r"(a[1]), "r"(a[2]), "r"(a[3]), "r"(b0), "r"(b1));
}

// ---------------------------------------------------------------------------
// K0: W -> fp16, build permuted att2
// ---------------------------------------------------------------------------
__global__ __launch_bounds__(256) void k0_prep(
    const float* __restrict__ W, const float* __restrict__ attW)
{
    int i = blockIdx.x * 256 + threadIdx.x;
    if (i < 12800) {
        float2 v = ((const float2*)W)[i];
        ((unsigned*)g_wh)[i] = h2b(v.x, v.y);
    }
    if (i < 32) {
        int sub = i >> 2, j = i & 3;
        int c = sub >> 1, h = sub & 1;
        int f = 16 * h + 8 * (j >> 1) + 2 * c + (j & 1);
        g_att2p[i] = attW[32 + f];
    }
}

// ---------------------------------------------------------------------------
// K1: root transform + attention dot + zero-init + x->fp16 copy
// ---------------------------------------------------------------------------
__global__ __launch_bounds__(256) void k1_node(
    const float* __restrict__ x, const float* __restrict__ rootW,
    const float* __restrict__ attW, const float* __restrict__ bias)
{
    __shared__ __align__(16) float Rs[1024];
    __shared__ float a1s[32], bsh[32];
    int tid = threadIdx.x;
    ((float4*)Rs)[tid] = ((const float4*)rootW)[tid];
    if (tid < 32) { a1s[tid] = attW[tid]; bsh[tid] = bias[tid]; }
    __syncthreads();

    int n = blockIdx.x * 256 + tid;
    if (n >= NN) return;

    float xv[32];
    const float4* xp = (const float4*)(x + (size_t)n * 32);
#pragma unroll
    for (int j = 0; j < 8; j++) {
        float4 t = xp[j];
        xv[4*j] = t.x; xv[4*j+1] = t.y; xv[4*j+2] = t.z; xv[4*j+3] = t.w;
    }
    uint4* xhp = ((uint4*)g_xh) + (size_t)n * 4;
#pragma unroll
    for (int j = 0; j < 4; j++) {
        uint4 h;
        h.x = h2b(xv[8*j],   xv[8*j+1]);
        h.y = h2b(xv[8*j+2], xv[8*j+3]);
        h.z = h2b(xv[8*j+4], xv[8*j+5]);
        h.w = h2b(xv[8*j+6], xv[8*j+7]);
        xhp[j] = h;
    }

    u64 acc[16];
#pragma unroll
    for (int m = 0; m < 16; m++) acc[m] = pack2(0.f, 0.f);
#pragma unroll
    for (int f = 0; f < 32; f++) {
        u64 xf = pack2(xv[f], xv[f]);
        const ulonglong2* rp = (const ulonglong2*)(Rs + f * 32);
#pragma unroll
        for (int j = 0; j < 8; j++) {
            ulonglong2 w = rp[j];
            acc[2*j]   = fma2(xf, w.x, acc[2*j]);
            acc[2*j+1] = fma2(xf, w.y, acc[2*j+1]);
        }
    }
    float xr[32];
#pragma unroll
    for (int m = 0; m < 16; m++) unpack2(acc[m], xr[2*m], xr[2*m+1]);

    float rd = 0.f;
#pragma unroll
    for (int o = 0; o < 32; o++) rd += xr[o] * a1s[o];
    g_rdot[n]  = rd;
    g_denom[n] = 0.f;

    float4* xrbp = (float4*)(g_xrb + (size_t)n * 32);
    float4* accp = (float4*)(g_acc + (size_t)n * 32);
#pragma unroll
    for (int j = 0; j < 8; j++) {
        float4 v;
        v.x = xr[4*j]   + bsh[4*j];
        v.y = xr[4*j+1] + bsh[4*j+1];
        v.z = xr[4*j+2] + bsh[4*j+2];
        v.w = xr[4*j+3] + bsh[4*j+3];
        xrbp[j] = v;
        accp[j] = make_float4(0.f, 0.f, 0.f, 0.f);
    }
}

// ---------------------------------------------------------------------------
// K2: raw mma.m16n8k16. 8 warps/block, 128 nodes/block (16/warp).
//   W (51200B) + A (8192B) staged in smem, XOR-swizzled for ldmatrix.
//   C regs -> f16x2 -> 2x STG.128/thread/k into PERMUTED xw'.
// ---------------------------------------------------------------------------
__global__ __launch_bounds__(256) void k2_mma()
{
    extern __shared__ __align__(16) char smraw[];
    uint4* Wd = (uint4*)smraw;                 // 3200 uint4
    uint4* Ad = (uint4*)(smraw + 51200);       // 512 uint4

    int tid = threadIdx.x;
    {
        const uint4* wsrc = (const uint4*)g_wh;
#pragma unroll
        for (int i = 0; i < 13; i++) {
            int ch = tid + 256 * i;
            if (ch < 3200) {
                int kk = ch >> 7, r = (ch >> 2) & 31, c = ch & 3;
                Wd[kk * 128 + r * 4 + (c ^ ((r >> 1) & 3))] = wsrc[ch];
            }
        }
        int n0g = blockIdx.x * 128;
        const uint4* xsrc = ((const uint4*)g_xh) + (size_t)n0g * 4;
#pragma unroll
        for (int i = 0; i < 2; i++) {
            int ch = tid + 256 * i;
            int nd = ch >> 2, c = ch & 3;
            Ad[nd * 4 + (c ^ ((nd >> 1) & 3))] = xsrc[ch];
        }
    }
    __syncthreads();

    int lane = tid & 31, warp = tid >> 5;
    int n0 = warp * 16;
    unsigned Ab = sm_u32(Ad), Wb = sm_u32(Wd);

    // A fragments (held for all 25 kernels)
    int Lr = lane & 7, mg = lane >> 3;
    int anode = n0 + Lr + 8 * (mg & 1);
    int acb = mg >> 1;
    unsigned A0[4], A1[4];
    ldsm4(A0[0], A0[1], A0[2], A0[3],
          Ab + anode * 64 + (((acb)     ^ ((anode >> 1) & 3)) << 4));
    ldsm4(A1[0], A1[1], A1[2], A1[3],
          Ab + anode * 64 + (((acb + 2) ^ ((anode >> 1) & 3)) << 4));

    unsigned wrow = Wb + lane * 64;
    unsigned bsw0 = ((0 ^ ((lane >> 1) & 3)) << 4);
    unsigned bsw1 = ((1 ^ ((lane >> 1) & 3)) << 4);
    unsigned bsw2 = ((2 ^ ((lane >> 1) & 3)) << 4);
    unsigned bsw3 = ((3 ^ ((lane >> 1) & 3)) << 4);

    char* outb = ((char*)g_xwp)
               + (size_t)(blockIdx.x * 128 + n0 + (lane >> 2)) * 1600
               + (lane & 3) * 16;

#pragma unroll 1
    for (int k = 0; k < 25; k++) {
        unsigned wk = wrow + k * 2048;
        float c0[4] = {0,0,0,0}, c1[4] = {0,0,0,0};
        float c2[4] = {0,0,0,0}, c3[4] = {0,0,0,0};
        unsigned b0, b1, b2, b3;
        ldsm4t(b0, b1, b2, b3, wk + bsw0);
        mma16816(c0, A0, b0, b1); mma16816(c0, A1, b2, b3);
        ldsm4t(b0, b1, b2, b3, wk + bsw1);
        mma16816(c1, A0, b0, b1); mma16816(c1, A1, b2, b3);
        ldsm4t(b0, b1, b2, b3, wk + bsw2);
        mma16816(c2, A0, b0, b1); mma16816(c2, A1, b2, b3);
        ldsm4t(b0, b1, b2, b3, wk + bsw3);
        mma16816(c3, A0, b0, b1); mma16816(c3, A1, b2, b3);

        uint4 v0, v1;
        v0.x = h2b(c0[0], c0[1]); v0.y = h2b(c1[0], c1[1]);
        v0.z = h2b(c2[0], c2[1]); v0.w = h2b(c3[0], c3[1]);
        v1.x = h2b(c0[2], c0[3]); v1.y = h2b(c1[2], c1[3]);
        v1.z = h2b(c2[2], c2[3]); v1.w = h2b(c3[2], c3[3]);
        *(uint4*)(outb + k * 64) = v0;                   // row r
        *(uint4*)(outb + k * 64 + 8 * 1600) = v1;        // row r+8
    }
}

// ---------------------------------------------------------------------------
// K3: single edge pass, 8 lanes/edge, permuted fp16 gather (round-5 shape).
// ---------------------------------------------------------------------------
__global__ __launch_bounds__(256) void k3_edge(
    const int* __restrict__ ei, const float* __restrict__ pseudo)
{
    int t = blockIdx.x * 256 + threadIdx.x;
    int e   = t >> 3;
    int sub = t & 7;

    int row = __ldg(ei + e);
    int col = __ldg(ei + NE + e);
    float2 pr = __ldg(((const float2*)pseudo) + e);
    float p0 = pr.x * 4.f, p1 = pr.y * 4.f;
    float fl0 = floorf(p0), fl1 = floorf(p1);
    float fr0 = p0 - fl0,   fr1 = p1 - fl1;
    int i0 = (int)fl0, i1 = (int)fl1;           // <= 3 always

    const uint2* base = g_xwp + (size_t)col * 200 + sub;
    float m0 = 0.f, m1 = 0.f, m2 = 0.f, m3 = 0.f;
#pragma unroll
    for (int s = 0; s < 4; s++) {
        int o0 = s & 1, o1 = (s >> 1) & 1;
        float b = (o0 ? fr0 : 1.f - fr0) * (o1 ? fr1 : 1.f - fr1);
        int w = (i0 + o0) + 5 * (i1 + o1);
        uint2 v = __ldg(base + w * 8);
        float2 f0 = __half22float2(*reinterpret_cast<const __half2*>(&v.x));
        float2 f1 = __half22float2(*reinterpret_cast<const __half2*>(&v.y));
        m0 = fmaf(b, f0.x, m0); m1 = fmaf(b, f0.y, m1);
        m2 = fmaf(b, f1.x, m2); m3 = fmaf(b, f1.y, m3);
    }

    float4 a2 = __ldg(((const float4*)g_att2p) + sub);
    float d = m0 * a2.x + m1 * a2.y + m2 * a2.z + m3 * a2.w;
    d += __shfl_xor_sync(0xffffffffu, d, 1);
    d += __shfl_xor_sync(0xffffffffu, d, 2);
    d += __shfl_xor_sync(0xffffffffu, d, 4);

    float alpha = d + __ldg(g_rdot + row);
    alpha = (alpha > 0.f) ? alpha : 0.2f * alpha;    // leaky relu
    float ex = __expf(alpha);       // softmax max-shift cancels in the ratio

    if (sub == 0) atomicAdd(g_denom + row, ex);

    float* ap = g_acc + (size_t)row * 32 + sub * 4;
    asm volatile("red.global.add.v4.f32 [%0], {%1,%2,%3,%4};"
                 :: "l"(ap), "f"(m0 * ex), "f"(m1 * ex),
                    "f"(m2 * ex), "f"(m3 * ex)
                 : "memory");
}

// ---------------------------------------------------------------------------
// K4: out = unpermute(acc) / (denom + 1e-16) + (x_root + bias)
// ---------------------------------------------------------------------------
__global__ __launch_bounds__(256) void k4_out(float* __restrict__ out)
{
    int i = blockIdx.x * 256 + threadIdx.x;
    int n = i >> 3, g = i & 7;
    float r = 1.f / (g_denom[n] + 1e-16f);
    const float* ap = g_acc + (size_t)n * 32;
    int h  = (g >> 2) & 1;
    int bb = (g >> 1) & 1;
    int pos0 = 8 * ((2 * g) & 3)     + 4 * h + 2 * bb;
    int pos1 = 8 * ((2 * g + 1) & 3) + 4 * h + 2 * bb;
    float2 u0 = *(const float2*)(ap + pos0);
    float2 u1 = *(const float2*)(ap + pos1);
    float4 xr = ((const float4*)g_xrb)[i];
    float4 o;
    o.x = fmaf(u0.x, r, xr.x);
    o.y = fmaf(u0.y, r, xr.y);
    o.z = fmaf(u1.x, r, xr.z);
    o.w = fmaf(u1.y, r, xr.w);
    ((float4*)out)[i] = o;
}

extern "C" void kernel_launch(void* const* d_in, const int* in_sizes, int n_in,
                              void* d_out, int out_size)
{
    const float* x      = (const float*)d_in[0];
    const int*   ei     = (const int*)d_in[1];
    const float* pseudo = (const float*)d_in[2];
    const float* W      = (const float*)d_in[3];
    const float* rootW  = (const float*)d_in[4];
    const float* attW   = (const float*)d_in[5];
    const float* bias   = (const float*)d_in[6];
    float* out = (float*)d_out;

    static bool attr_set = false;
    if (!attr_set) {
        cudaFuncSetAttribute(k2_mma,
            cudaFuncAttributeMaxDynamicSharedMemorySize, 59392);
        attr_set = true;
    }

    k0_prep<<<50, 256>>>(W, attW);
    k1_node<<<(NN + 255) / 256, 256>>>(x, rootW, attW, bias);
    k2_mma <<<NNP / 128, 256, 59392>>>();
    k3_edge<<<(NE * 8) / 256, 256>>>(ei, pseudo);
    k4_out <<<(NN * 32 / 4) / 256, 256>>>(out);
}

// round 8
// speedup vs baseline: 1.6301x; 1.0482x over previous
#include <cuda_runtime.h>
#include <cuda_fp16.h>

#define NN 100000
#define NNP 100096          // padded to 128-node k2 blocks (782 * 128)
#define NE 1600000

// fp16 copies of x and W (+rootW as 26th kernel)
__device__ __half g_xh[(size_t)NNP * 32];
__device__ __half g_wh[26 * 32 * 32];
// xw' (PERMUTED feature layout) fp16: [NNP][25 kernels][64B]
__device__ uint2 g_xwp[(size_t)NNP * 200];
__device__ float g_att1p[32];                // attW[0..32) permuted
__device__ float g_att2p[32];                // attW[32..64) permuted
__device__ float g_biasp[32];                // bias permuted
__device__ float g_acc[(size_t)NN * 32];     // permuted space
__device__ float g_xrb[(size_t)NNP * 32];    // x_root, PERMUTED fp32 (from k2)
__device__ float g_rdot[NNP];
__device__ float g_denom[NN];

__device__ __forceinline__ unsigned h2b(float a, float b) {
    unsigned r; asm("cvt.rn.f16x2.f32 %0,%2,%1;" : "=r"(r) : "f"(a), "f"(b));
    return r;   // low half = a
}
__device__ __forceinline__ unsigned sm_u32(const void* p) {
    unsigned r;
    asm("{.reg .u64 t; cvta.to.shared.u64 t, %1; cvt.u32.u64 %0, t;}"
        : "=r"(r) : "l"(p));
    return r;
}
__device__ __forceinline__ void ldsm4(unsigned& r0, unsigned& r1,
                                      unsigned& r2, unsigned& r3, unsigned a) {
    asm volatile("ldmatrix.sync.aligned.m8n8.x4.shared.b16 {%0,%1,%2,%3}, [%4];"
                 : "=r"(r0), "=r"(r1), "=r"(r2), "=r"(r3) : "r"(a));
}
__device__ __forceinline__ void ldsm4t(unsigned& r0, unsigned& r1,
                                       unsigned& r2, unsigned& r3, unsigned a) {
    asm volatile("ldmatrix.sync.aligned.m8n8.x4.trans.shared.b16 {%0,%1,%2,%3}, [%4];"
                 : "=r"(r0), "=r"(r1), "=r"(r2), "=r"(r3) : "r"(a));
}
__device__ __forceinline__ void mma16816(float* c, const unsigned* a,
                                         unsigned b0, unsigned b1) {
    asm volatile("mma.sync.aligned.m16n8k16.row.col.f32.f16.f16.f32 "
                 "{%0,%1,%2,%3}, {%4,%5,%6,%7}, {%8,%9}, {%0,%1,%2,%3};"
                 : "+f"(c[0]), "+f"(c[1]), "+f"(c[2]), "+f"(c[3])
                 : "r"(a[0]), "r"(a[1]), "r"(a[2]), "r"(a[3]), "r"(b0), "r"(b1));
}

// ---------------------------------------------------------------------------
// K0: W+rootW -> fp16, permuted att1/att2/bias tables, zero acc/denom
// ---------------------------------------------------------------------------
__global__ __launch_bounds__(256) void k0_prep(
    const float* __restrict__ W, const float* __restrict__ rootW,
    const float* __restrict__ attW, const float* __restrict__ bias)
{
    int i = blockIdx.x * 256 + threadIdx.x;          // 800000 threads
    ((float4*)g_acc)[i] = make_float4(0.f, 0.f, 0.f, 0.f);
    if (i < 25000)
        ((float4*)g_denom)[i] = make_float4(0.f, 0.f, 0.f, 0.f);
    if (i < 12800) {                                  // 25 W_k
        float2 v = ((const float2*)W)[i];
        ((unsigned*)g_wh)[i] = h2b(v.x, v.y);
    } else if (i < 13312) {                           // rootW as kernel 25
        float2 v = ((const float2*)rootW)[i - 12800];
        ((unsigned*)g_wh)[i] = h2b(v.x, v.y);
    }
    if (i < 32) {
        int sub = i >> 2, j = i & 3;
        int c = sub >> 1, h = sub & 1;
        int f = 16 * h + 8 * (j >> 1) + 2 * c + (j & 1);
        g_att1p[i] = attW[f];
        g_att2p[i] = attW[32 + f];
        g_biasp[i] = bias[f];
    }
}

// ---------------------------------------------------------------------------
// K1: x -> fp16 copy only
// ---------------------------------------------------------------------------
__global__ __launch_bounds__(256) void k1_conv(const float* __restrict__ x)
{
    int n = blockIdx.x * 256 + threadIdx.x;
    if (n >= NN) return;
    const float4* xp = (const float4*)(x + (size_t)n * 32);
    uint4* xhp = ((uint4*)g_xh) + (size_t)n * 4;
#pragma unroll
    for (int j = 0; j < 4; j++) {
        float4 t0 = xp[2*j], t1 = xp[2*j+1];
        uint4 h;
        h.x = h2b(t0.x, t0.y); h.y = h2b(t0.z, t0.w);
        h.z = h2b(t1.x, t1.y); h.w = h2b(t1.z, t1.w);
        xhp[j] = h;
    }
}

// ---------------------------------------------------------------------------
// K2: raw mma.m16n8k16, 26 kernels (25 spline + root).
//   8 warps/block, 128 nodes/block (16/warp). W+A smem, XOR-swizzled.
//   k<25: fp16 STG.128 into permuted xw'. k=25: fp32 x_root + rdot epilogue.
// ---------------------------------------------------------------------------
__global__ __launch_bounds__(256) void k2_mma()
{
    extern __shared__ __align__(16) char smraw[];
    uint4* Wd = (uint4*)smraw;                 // 3328 uint4 (26 * 2048B)
    uint4* Ad = (uint4*)(smraw + 53248);       // 512 uint4

    int tid = threadIdx.x;
    {
        const uint4* wsrc = (const uint4*)g_wh;
#pragma unroll
        for (int i = 0; i < 13; i++) {
            int ch = tid + 256 * i;            // 3328 exact
            int kk = ch >> 7, r = (ch >> 2) & 31, c = ch & 3;
            Wd[kk * 128 + r * 4 + (c ^ ((r >> 1) & 3))] = wsrc[ch];
        }
        int n0g = blockIdx.x * 128;
        const uint4* xsrc = ((const uint4*)g_xh) + (size_t)n0g * 4;
#pragma unroll
        for (int i = 0; i < 2; i++) {
            int ch = tid + 256 * i;
            int nd = ch >> 2, c = ch & 3;
            Ad[nd * 4 + (c ^ ((nd >> 1) & 3))] = xsrc[ch];
        }
    }
    __syncthreads();

    int lane = tid & 31, warp = tid >> 5;
    int n0 = warp * 16;
    unsigned Ab = sm_u32(Ad), Wb = sm_u32(Wd);

    int Lr = lane & 7, mg = lane >> 3;
    int anode = n0 + Lr + 8 * (mg & 1);
    int acb = mg >> 1;
    unsigned A0[4], A1[4];
    ldsm4(A0[0], A0[1], A0[2], A0[3],
          Ab + anode * 64 + (((acb)     ^ ((anode >> 1) & 3)) << 4));
    ldsm4(A1[0], A1[1], A1[2], A1[3],
          Ab + anode * 64 + (((acb + 2) ^ ((anode >> 1) & 3)) << 4));

    unsigned wrow = Wb + lane * 64;
    unsigned bsw0 = ((0 ^ ((lane >> 1) & 3)) << 4);
    unsigned bsw1 = ((1 ^ ((lane >> 1) & 3)) << 4);
    unsigned bsw2 = ((2 ^ ((lane >> 1) & 3)) << 4);
    unsigned bsw3 = ((3 ^ ((lane >> 1) & 3)) << 4);

    char* outb = ((char*)g_xwp)
               + (size_t)(blockIdx.x * 128 + n0 + (lane >> 2)) * 1600
               + (lane & 3) * 16;

#pragma unroll 1
    for (int k = 0; k < 25; k++) {
        unsigned wk = wrow + k * 2048;
        float c0[4] = {0,0,0,0}, c1[4] = {0,0,0,0};
        float c2[4] = {0,0,0,0}, c3[4] = {0,0,0,0};
        unsigned b0, b1, b2, b3;
        ldsm4t(b0, b1, b2, b3, wk + bsw0);
        mma16816(c0, A0, b0, b1); mma16816(c0, A1, b2, b3);
        ldsm4t(b0, b1, b2, b3, wk + bsw1);
        mma16816(c1, A0, b0, b1); mma16816(c1, A1, b2, b3);
        ldsm4t(b0, b1, b2, b3, wk + bsw2);
        mma16816(c2, A0, b0, b1); mma16816(c2, A1, b2, b3);
        ldsm4t(b0, b1, b2, b3, wk + bsw3);
        mma16816(c3, A0, b0, b1); mma16816(c3, A1, b2, b3);

        uint4 v0, v1;
        v0.x = h2b(c0[0], c0[1]); v0.y = h2b(c1[0], c1[1]);
        v0.z = h2b(c2[0], c2[1]); v0.w = h2b(c3[0], c3[1]);
        v1.x = h2b(c0[2], c0[3]); v1.y = h2b(c1[2], c1[3]);
        v1.z = h2b(c2[2], c2[3]); v1.w = h2b(c3[2], c3[3]);
        *(uint4*)(outb + k * 64) = v0;                   // row r
        *(uint4*)(outb + k * 64 + 8 * 1600) = v1;        // row r+8
    }

    // k = 25: root transform (fp32 permuted) + rdot
    {
        unsigned wk = wrow + 25 * 2048;
        float c0[4] = {0,0,0,0}, c1[4] = {0,0,0,0};
        float c2[4] = {0,0,0,0}, c3[4] = {0,0,0,0};
        unsigned b0, b1, b2, b3;
        ldsm4t(b0, b1, b2, b3, wk + bsw0);
        mma16816(c0, A0, b0, b1); mma16816(c0, A1, b2, b3);
        ldsm4t(b0, b1, b2, b3, wk + bsw1);
        mma16816(c1, A0, b0, b1); mma16816(c1, A1, b2, b3);
        ldsm4t(b0, b1, b2, b3, wk + bsw2);
        mma16816(c2, A0, b0, b1); mma16816(c2, A1, b2, b3);
        ldsm4t(b0, b1, b2, b3, wk + bsw3);
        mma16816(c3, A0, b0, b1); mma16816(c3, A1, b2, b3);

        int node = blockIdx.x * 128 + n0 + (lane >> 2);
        float* xo = g_xrb + (size_t)node * 32 + (lane & 3) * 8;
        *(float4*)(xo)           = make_float4(c0[0], c0[1], c1[0], c1[1]);
        *(float4*)(xo + 4)       = make_float4(c2[0], c2[1], c3[0], c3[1]);
        *(float4*)(xo + 256)     = make_float4(c0[2], c0[3], c1[2], c1[3]);
        *(float4*)(xo + 260)     = make_float4(c2[2], c2[3], c3[2], c3[3]);

        float4 a1a = __ldg(((const float4*)g_att1p) + (lane & 3) * 2);
        float4 a1b = __ldg(((const float4*)g_att1p) + (lane & 3) * 2 + 1);
        float dr  = c0[0]*a1a.x + c0[1]*a1a.y + c1[0]*a1a.z + c1[1]*a1a.w
                  + c2[0]*a1b.x + c2[1]*a1b.y + c3[0]*a1b.z + c3[1]*a1b.w;
        float dr8 = c0[2]*a1a.x + c0[3]*a1a.y + c1[2]*a1a.z + c1[3]*a1a.w
                  + c2[2]*a1b.x + c2[3]*a1b.y + c3[2]*a1b.z + c3[3]*a1b.w;
        dr  += __shfl_xor_sync(0xffffffffu, dr, 1);
        dr  += __shfl_xor_sync(0xffffffffu, dr, 2);
        dr8 += __shfl_xor_sync(0xffffffffu, dr8, 1);
        dr8 += __shfl_xor_sync(0xffffffffu, dr8, 2);
        if ((lane & 3) == 0) {
            g_rdot[node]     = dr;
            g_rdot[node + 8] = dr8;
        }
    }
}

// ---------------------------------------------------------------------------
// K3: single edge pass, 8 lanes/edge, HFMA2 tap accumulation.
// ---------------------------------------------------------------------------
__global__ __launch_bounds__(256) void k3_edge(
    const int* __restrict__ ei, const float* __restrict__ pseudo)
{
    int t = blockIdx.x * 256 + threadIdx.x;
    int e   = t >> 3;
    int sub = t & 7;

    int row = __ldg(ei + e);
    int col = __ldg(ei + NE + e);
    float2 pr = __ldg(((const float2*)pseudo) + e);
    float p0 = pr.x * 4.f, p1 = pr.y * 4.f;
    float fl0 = floorf(p0), fl1 = floorf(p1);
    float fr0 = p0 - fl0,   fr1 = p1 - fl1;
    int i0 = (int)fl0, i1 = (int)fl1;           // <= 3 (pseudo in [0,1))
    int w0 = i0 + 5 * i1;

    const uint2* base = g_xwp + (size_t)col * 200 + sub;
    uint2 v0 = __ldg(base + w0 * 8);
    uint2 v1 = __ldg(base + (w0 + 1) * 8);
    uint2 v2 = __ldg(base + (w0 + 5) * 8);
    uint2 v3 = __ldg(base + (w0 + 6) * 8);

    float g0 = 1.f - fr0, g1 = 1.f - fr1;
    unsigned u00 = h2b(g0 * g1,  g0 * g1);
    unsigned u10 = h2b(fr0 * g1, fr0 * g1);
    unsigned u01 = h2b(g0 * fr1, g0 * fr1);
    unsigned u11 = h2b(fr0 * fr1, fr0 * fr1);

    __half2 a01, a23;
    a01 = __hmul2(*(__half2*)&u00, *(__half2*)&v0.x);
    a23 = __hmul2(*(__half2*)&u00, *(__half2*)&v0.y);
    a01 = __hfma2(*(__half2*)&u10, *(__half2*)&v1.x, a01);
    a23 = __hfma2(*(__half2*)&u10, *(__half2*)&v1.y, a23);
    a01 = __hfma2(*(__half2*)&u01, *(__half2*)&v2.x, a01);
    a23 = __hfma2(*(__half2*)&u01, *(__half2*)&v2.y, a23);
    a01 = __hfma2(*(__half2*)&u11, *(__half2*)&v3.x, a01);
    a23 = __hfma2(*(__half2*)&u11, *(__half2*)&v3.y, a23);

    float2 f01 = __half22float2(a01);
    float2 f23 = __half22float2(a23);
    float m0 = f01.x, m1 = f01.y, m2 = f23.x, m3 = f23.y;

    float4 a2 = __ldg(((const float4*)g_att2p) + sub);
    float d = m0 * a2.x + m1 * a2.y + m2 * a2.z + m3 * a2.w;
    d += __shfl_xor_sync(0xffffffffu, d, 1);
    d += __shfl_xor_sync(0xffffffffu, d, 2);
    d += __shfl_xor_sync(0xffffffffu, d, 4);

    float alpha = d + __ldg(g_rdot + row);
    alpha = (alpha > 0.f) ? alpha : 0.2f * alpha;    // leaky relu
    float ex = __expf(alpha);       // softmax max-shift cancels in the ratio

    if (sub == 0) atomicAdd(g_denom + row, ex);

    float* ap = g_acc + (size_t)row * 32 + sub * 4;
    asm volatile("red.global.add.v4.f32 [%0], {%1,%2,%3,%4};"
                 :: "l"(ap), "f"(m0 * ex), "f"(m1 * ex),
                    "f"(m2 * ex), "f"(m3 * ex)
                 : "memory");
}

// ---------------------------------------------------------------------------
// K4: out = unpermute( acc/(denom+1e-16) + x_root_perm + bias_perm )
// ---------------------------------------------------------------------------
__global__ __launch_bounds__(256) void k4_out(float* __restrict__ out)
{
    int i = blockIdx.x * 256 + threadIdx.x;     // 800000 = NN*8
    int n = i >> 3, g = i & 7;
    float r = 1.f / (g_denom[n] + 1e-16f);
    const float* ap  = g_acc + (size_t)n * 32;
    const float* xp_ = g_xrb + (size_t)n * 32;
    int h  = (g >> 2) & 1;
    int bb = (g >> 1) & 1;
    int pos0 = 8 * ((2 * g) & 3)     + 4 * h + 2 * bb;
    int pos1 = 8 * ((2 * g + 1) & 3) + 4 * h + 2 * bb;
    float2 u0 = *(const float2*)(ap + pos0);
    float2 u1 = *(const float2*)(ap + pos1);
    float2 x0 = *(const float2*)(xp_ + pos0);
    float2 x1 = *(const float2*)(xp_ + pos1);
    float2 b0 = *(const float2*)(g_biasp + pos0);
    float2 b1 = *(const float2*)(g_biasp + pos1);
    float4 o;
    o.x = fmaf(u0.x, r, x0.x + b0.x);
    o.y = fmaf(u0.y, r, x0.y + b0.y);
    o.z = fmaf(u1.x, r, x1.x + b1.x);
    o.w = fmaf(u1.y, r, x1.y + b1.y);
    ((float4*)out)[i] = o;
}

extern "C" void kernel_launch(void* const* d_in, const int* in_sizes, int n_in,
                              void* d_out, int out_size)
{
    const float* x      = (const float*)d_in[0];
    const int*   ei     = (const int*)d_in[1];
    const float* pseudo = (const float*)d_in[2];
    const float* W      = (const float*)d_in[3];
    const float* rootW  = (const float*)d_in[4];
    const float* attW   = (const float*)d_in[5];
    const float* bias   = (const float*)d_in[6];
    float* out = (float*)d_out;

    static bool attr_set = false;
    if (!attr_set) {
        cudaFuncSetAttribute(k2_mma,
            cudaFuncAttributeMaxDynamicSharedMemorySize, 61440);
        attr_set = true;
    }

    k0_prep<<<3125, 256>>>(W, rootW, attW, bias);
    k1_conv<<<(NN + 255) / 256, 256>>>(x);
    k2_mma <<<NNP / 128, 256, 61440>>>();
    k3_edge<<<(NE * 8) / 256, 256>>>(ei, pseudo);
    k4_out <<<3125, 256>>>(out);
}

// round 9
// speedup vs baseline: 1.6472x; 1.0105x over previous
#include <cuda_runtime.h>
#include <cuda_fp16.h>

#define NN 100000
#define NNP 100096          // padded to 128-node k2 blocks (782 * 128)
#define NE 1600000

// fp16 copy of x
__device__ __half g_xh[(size_t)NNP * 32];
// xw' (PERMUTED feature layout) fp16: [NNP][25 kernels][64B]
__device__ uint2 g_xwp[(size_t)NNP * 200];
__device__ float g_att1p[32];                // attW[0..32) permuted
__device__ float g_att2p[32];                // attW[32..64) permuted
__device__ float g_biasp[32];                // bias permuted
__device__ float g_acc[(size_t)NN * 32];     // permuted space
__device__ float g_xrb[(size_t)NNP * 32];    // x_root, PERMUTED fp32 (from k2)
__device__ float g_rdot[NNP];
__device__ float g_denom[NN];

__device__ __forceinline__ unsigned h2b(float a, float b) {
    unsigned r; asm("cvt.rn.f16x2.f32 %0,%2,%1;" : "=r"(r) : "f"(a), "f"(b));
    return r;   // low half = a
}
__device__ __forceinline__ unsigned sm_u32(const void* p) {
    unsigned r;
    asm("{.reg .u64 t; cvta.to.shared.u64 t, %1; cvt.u32.u64 %0, t;}"
        : "=r"(r) : "l"(p));
    return r;
}
__device__ __forceinline__ void ldsm4(unsigned& r0, unsigned& r1,
                                      unsigned& r2, unsigned& r3, unsigned a) {
    asm volatile("ldmatrix.sync.aligned.m8n8.x4.shared.b16 {%0,%1,%2,%3}, [%4];"
                 : "=r"(r0), "=r"(r1), "=r"(r2), "=r"(r3) : "r"(a));
}
__device__ __forceinline__ void ldsm4t(unsigned& r0, unsigned& r1,
                                       unsigned& r2, unsigned& r3, unsigned a) {
    asm volatile("ldmatrix.sync.aligned.m8n8.x4.trans.shared.b16 {%0,%1,%2,%3}, [%4];"
                 : "=r"(r0), "=r"(r1), "=r"(r2), "=r"(r3) : "r"(a));
}
__device__ __forceinline__ void mma16816(float* c, const unsigned* a,
                                         unsigned b0, unsigned b1) {
    asm volatile("mma.sync.aligned.m16n8k16.row.col.f32.f16.f16.f32 "
                 "{%0,%1,%2,%3}, {%4,%5,%6,%7}, {%8,%9}, {%0,%1,%2,%3};"
                 : "+f"(c[0]), "+f"(c[1]), "+f"(c[2]), "+f"(c[3])
                 : "r"(a[0]), "r"(a[1]), "r"(a[2]), "r"(a[3]), "r"(b0), "r"(b1));
}

// ---------------------------------------------------------------------------
// K0 (1 warp): permuted att1/att2/bias tables
// ---------------------------------------------------------------------------
__global__ void k0_tables(const float* __restrict__ attW,
                          const float* __restrict__ bias)
{
    int i = threadIdx.x;                 // 32 threads
    int sub = i >> 2, j = i & 3;
    int c = sub >> 1, h = sub & 1;
    int f = 16 * h + 8 * (j >> 1) + 2 * c + (j & 1);
    g_att1p[i] = attW[f];
    g_att2p[i] = attW[32 + f];
    g_biasp[i] = bias[f];
}

// ---------------------------------------------------------------------------
// K1: x -> fp16 copy + zero acc/denom
// ---------------------------------------------------------------------------
__global__ __launch_bounds__(256) void k1_conv(const float* __restrict__ x)
{
    int n = blockIdx.x * 256 + threadIdx.x;
    if (n >= NN) return;
    const float4* xp = (const float4*)(x + (size_t)n * 32);
    uint4* xhp = ((uint4*)g_xh) + (size_t)n * 4;
#pragma unroll
    for (int j = 0; j < 4; j++) {
        float4 t0 = xp[2*j], t1 = xp[2*j+1];
        uint4 h;
        h.x = h2b(t0.x, t0.y); h.y = h2b(t0.z, t0.w);
        h.z = h2b(t1.x, t1.y); h.w = h2b(t1.z, t1.w);
        xhp[j] = h;
    }
    float4* accp = (float4*)(g_acc + (size_t)n * 32);
#pragma unroll
    for (int j = 0; j < 8; j++)
        accp[j] = make_float4(0.f, 0.f, 0.f, 0.f);
    g_denom[n] = 0.f;
}

// ---------------------------------------------------------------------------
// K2: raw mma.m16n8k16, 26 kernels (25 spline + root).
//   W converted fp32->fp16 during smem staging (no separate pass).
//   k<25: fp16 STG.128 into permuted xw'. k=25: fp32 x_root + rdot epilogue.
// ---------------------------------------------------------------------------
__global__ __launch_bounds__(256) void k2_mma(
    const float* __restrict__ W, const float* __restrict__ rootW)
{
    extern __shared__ __align__(16) char smraw[];
    uint4* Wd = (uint4*)smraw;                 // 3328 uint4 (26 * 2048B)
    uint4* Ad = (uint4*)(smraw + 53248);       // 512 uint4

    int tid = threadIdx.x;
    {
#pragma unroll
        for (int i = 0; i < 13; i++) {
            int ch = tid + 256 * i;            // 3328 exact
            int kk = ch >> 7, r = (ch >> 2) & 31, c = ch & 3;
            const float* src = (kk < 25 ? W + kk * 1024 : rootW) + r * 32 + c * 8;
            float4 s0 = __ldg((const float4*)src);
            float4 s1 = __ldg((const float4*)src + 1);
            uint4 v;
            v.x = h2b(s0.x, s0.y); v.y = h2b(s0.z, s0.w);
            v.z = h2b(s1.x, s1.y); v.w = h2b(s1.z, s1.w);
            Wd[kk * 128 + r * 4 + (c ^ ((r >> 1) & 3))] = v;
        }
        int n0g = blockIdx.x * 128;
        const uint4* xsrc = ((const uint4*)g_xh) + (size_t)n0g * 4;
#pragma unroll
        for (int i = 0; i < 2; i++) {
            int ch = tid + 256 * i;
            int nd = ch >> 2, c = ch & 3;
            Ad[nd * 4 + (c ^ ((nd >> 1) & 3))] = xsrc[ch];
        }
    }
    __syncthreads();

    int lane = tid & 31, warp = tid >> 5;
    int n0 = warp * 16;
    unsigned Ab = sm_u32(Ad), Wb = sm_u32(Wd);

    int Lr = lane & 7, mg = lane >> 3;
    int anode = n0 + Lr + 8 * (mg & 1);
    int acb = mg >> 1;
    unsigned A0[4], A1[4];
    ldsm4(A0[0], A0[1], A0[2], A0[3],
          Ab + anode * 64 + (((acb)     ^ ((anode >> 1) & 3)) << 4));
    ldsm4(A1[0], A1[1], A1[2], A1[3],
          Ab + anode * 64 + (((acb + 2) ^ ((anode >> 1) & 3)) << 4));

    unsigned wrow = Wb + lane * 64;
    unsigned bsw0 = ((0 ^ ((lane >> 1) & 3)) << 4);
    unsigned bsw1 = ((1 ^ ((lane >> 1) & 3)) << 4);
    unsigned bsw2 = ((2 ^ ((lane >> 1) & 3)) << 4);
    unsigned bsw3 = ((3 ^ ((lane >> 1) & 3)) << 4);

    char* outb = ((char*)g_xwp)
               + (size_t)(blockIdx.x * 128 + n0 + (lane >> 2)) * 1600
               + (lane & 3) * 16;

#pragma unroll 1
    for (int k = 0; k < 25; k++) {
        unsigned wk = wrow + k * 2048;
        float c0[4] = {0,0,0,0}, c1[4] = {0,0,0,0};
        float c2[4] = {0,0,0,0}, c3[4] = {0,0,0,0};
        unsigned b0, b1, b2, b3;
        ldsm4t(b0, b1, b2, b3, wk + bsw0);
        mma16816(c0, A0, b0, b1); mma16816(c0, A1, b2, b3);
        ldsm4t(b0, b1, b2, b3, wk + bsw1);
        mma16816(c1, A0, b0, b1); mma16816(c1, A1, b2, b3);
        ldsm4t(b0, b1, b2, b3, wk + bsw2);
        mma16816(c2, A0, b0, b1); mma16816(c2, A1, b2, b3);
        ldsm4t(b0, b1, b2, b3, wk + bsw3);
        mma16816(c3, A0, b0, b1); mma16816(c3, A1, b2, b3);

        uint4 v0, v1;
        v0.x = h2b(c0[0], c0[1]); v0.y = h2b(c1[0], c1[1]);
        v0.z = h2b(c2[0], c2[1]); v0.w = h2b(c3[0], c3[1]);
        v1.x = h2b(c0[2], c0[3]); v1.y = h2b(c1[2], c1[3]);
        v1.z = h2b(c2[2], c2[3]); v1.w = h2b(c3[2], c3[3]);
        *(uint4*)(outb + k * 64) = v0;                   // row r
        *(uint4*)(outb + k * 64 + 8 * 1600) = v1;        // row r+8
    }

    // k = 25: root transform (fp32 permuted) + rdot
    {
        unsigned wk = wrow + 25 * 2048;
        float c0[4] = {0,0,0,0}, c1[4] = {0,0,0,0};
        float c2[4] = {0,0,0,0}, c3[4] = {0,0,0,0};
        unsigned b0, b1, b2, b3;
        ldsm4t(b0, b1, b2, b3, wk + bsw0);
        mma16816(c0, A0, b0, b1); mma16816(c0, A1, b2, b3);
        ldsm4t(b0, b1, b2, b3, wk + bsw1);
        mma16816(c1, A0, b0, b1); mma16816(c1, A1, b2, b3);
        ldsm4t(b0, b1, b2, b3, wk + bsw2);
        mma16816(c2, A0, b0, b1); mma16816(c2, A1, b2, b3);
        ldsm4t(b0, b1, b2, b3, wk + bsw3);
        mma16816(c3, A0, b0, b1); mma16816(c3, A1, b2, b3);

        int node = blockIdx.x * 128 + n0 + (lane >> 2);
        float* xo = g_xrb + (size_t)node * 32 + (lane & 3) * 8;
        *(float4*)(xo)       = make_float4(c0[0], c0[1], c1[0], c1[1]);
        *(float4*)(xo + 4)   = make_float4(c2[0], c2[1], c3[0], c3[1]);
        *(float4*)(xo + 256) = make_float4(c0[2], c0[3], c1[2], c1[3]);
        *(float4*)(xo + 260) = make_float4(c2[2], c2[3], c3[2], c3[3]);

        float4 a1a = __ldg(((const float4*)g_att1p) + (lane & 3) * 2);
        float4 a1b = __ldg(((const float4*)g_att1p) + (lane & 3) * 2 + 1);
        float dr  = c0[0]*a1a.x + c0[1]*a1a.y + c1[0]*a1a.z + c1[1]*a1a.w
                  + c2[0]*a1b.x + c2[1]*a1b.y + c3[0]*a1b.z + c3[1]*a1b.w;
        float dr8 = c0[2]*a1a.x + c0[3]*a1a.y + c1[2]*a1a.z + c1[3]*a1a.w
                  + c2[2]*a1b.x + c2[3]*a1b.y + c3[2]*a1b.z + c3[3]*a1b.w;
        dr  += __shfl_xor_sync(0xffffffffu, dr, 1);
        dr  += __shfl_xor_sync(0xffffffffu, dr, 2);
        dr8 += __shfl_xor_sync(0xffffffffu, dr8, 1);
        dr8 += __shfl_xor_sync(0xffffffffu, dr8, 2);
        if ((lane & 3) == 0) {
            g_rdot[node]     = dr;
            g_rdot[node + 8] = dr8;
        }
    }
}

// ---------------------------------------------------------------------------
// K3: single edge pass, 8 lanes/edge, paired-row LDG.128 gather.
//   qa = rows (w0, w0+1), qb = rows (w0+5, w0+6); lane sub<4 takes the low
//   row, sub>=4 the high row; taps combine via shfl.xor(4) + hadd2.
// ---------------------------------------------------------------------------
__global__ __launch_bounds__(256) void k3_edge(
    const int* __restrict__ ei, const float* __restrict__ pseudo)
{
    int t = blockIdx.x * 256 + threadIdx.x;
    int e   = t >> 3;
    int sub = t & 7;

    int row = __ldg(ei + e);
    int col = __ldg(ei + NE + e);
    float2 pr = __ldg(((const float2*)pseudo) + e);
    float p0 = pr.x * 4.f, p1 = pr.y * 4.f;
    float fl0 = floorf(p0), fl1 = floorf(p1);
    float fr0 = p0 - fl0,   fr1 = p1 - fl1;
    int w0 = (int)fl0 + 5 * (int)fl1;

    const char* basep = (const char*)g_xwp + (size_t)col * 1600 + (sub << 4);
    uint4 qa = __ldg((const uint4*)(basep + w0 * 64));          // taps (0,0)/(1,0)
    uint4 qb = __ldg((const uint4*)(basep + (w0 + 5) * 64));    // taps (0,1)/(1,1)

    float fa = (sub & 4) ? fr0 : (1.f - fr0);
    unsigned ua = h2b(fa * (1.f - fr1), fa * (1.f - fr1));
    unsigned ub = h2b(fa * fr1,         fa * fr1);
    __half2 ha = *(__half2*)&ua, hb = *(__half2*)&ub;

    __half2 h0 = __hmul2(ha, *(__half2*)&qa.x);
    __half2 h1 = __hmul2(ha, *(__half2*)&qa.y);
    __half2 h2 = __hmul2(ha, *(__half2*)&qa.z);
    __half2 h3 = __hmul2(ha, *(__half2*)&qa.w);
    h0 = __hfma2(hb, *(__half2*)&qb.x, h0);
    h1 = __hfma2(hb, *(__half2*)&qb.y, h1);
    h2 = __hfma2(hb, *(__half2*)&qb.z, h2);
    h3 = __hfma2(hb, *(__half2*)&qb.w, h3);

    unsigned uu;
    uu = __shfl_xor_sync(0xffffffffu, *(unsigned*)&h0, 4);
    h0 = __hadd2(h0, *(__half2*)&uu);
    uu = __shfl_xor_sync(0xffffffffu, *(unsigned*)&h1, 4);
    h1 = __hadd2(h1, *(__half2*)&uu);
    uu = __shfl_xor_sync(0xffffffffu, *(unsigned*)&h2, 4);
    h2 = __hadd2(h2, *(__half2*)&uu);
    uu = __shfl_xor_sync(0xffffffffu, *(unsigned*)&h3, 4);
    h3 = __hadd2(h3, *(__half2*)&uu);

    float2 f0 = __half22float2(h0), f1 = __half22float2(h1);
    float2 f2 = __half22float2(h2), f3 = __half22float2(h3);

    int s = sub & 3;
    float4 A0 = __ldg(((const float4*)g_att2p) + 2 * s);
    float4 A1 = __ldg(((const float4*)g_att2p) + 2 * s + 1);
    float d = f0.x*A0.x + f0.y*A0.y + f1.x*A0.z + f1.y*A0.w
            + f2.x*A1.x + f2.y*A1.y + f3.x*A1.z + f3.y*A1.w;
    d += __shfl_xor_sync(0xffffffffu, d, 1);
    d += __shfl_xor_sync(0xffffffffu, d, 2);

    float alpha = d + __ldg(g_rdot + row);
    alpha = (alpha > 0.f) ? alpha : 0.2f * alpha;    // leaky relu
    float ex = __expf(alpha);       // softmax max-shift cancels in the ratio

    if (sub == 0) atomicAdd(g_denom + row, ex);

    // lane sub<4 writes slots [8s, 8s+4); sub>=4 writes [8s+4, 8s+8)
    float* ap = g_acc + (size_t)row * 32 + s * 8 + (sub & 4);
    float4 wv = (sub & 4)
        ? make_float4(f2.x * ex, f2.y * ex, f3.x * ex, f3.y * ex)
        : make_float4(f0.x * ex, f0.y * ex, f1.x * ex, f1.y * ex);
    asm volatile("red.global.add.v4.f32 [%0], {%1,%2,%3,%4};"
                 :: "l"(ap), "f"(wv.x), "f"(wv.y), "f"(wv.z), "f"(wv.w)
                 : "memory");
}

// ---------------------------------------------------------------------------
// K4: out = unpermute( acc/(denom+1e-16) + x_root_perm + bias_perm )
// ---------------------------------------------------------------------------
__global__ __launch_bounds__(256) void k4_out(float* __restrict__ out)
{
    int i = blockIdx.x * 256 + threadIdx.x;     // 800000 = NN*8
    int n = i >> 3, g = i & 7;
    float r = 1.f / (g_denom[n] + 1e-16f);
    const float* ap  = g_acc + (size_t)n * 32;
    const float* xp_ = g_xrb + (size_t)n * 32;
    int h  = (g >> 2) & 1;
    int bb = (g >> 1) & 1;
    int pos0 = 8 * ((2 * g) & 3)     + 4 * h + 2 * bb;
    int pos1 = 8 * ((2 * g + 1) & 3) + 4 * h + 2 * bb;
    float2 u0 = *(const float2*)(ap + pos0);
    float2 u1 = *(const float2*)(ap + pos1);
    float2 x0 = *(const float2*)(xp_ + pos0);
    float2 x1 = *(const float2*)(xp_ + pos1);
    float2 b0 = *(const float2*)(g_biasp + pos0);
    float2 b1 = *(const float2*)(g_biasp + pos1);
    float4 o;
    o.x = fmaf(u0.x, r, x0.x + b0.x);
    o.y = fmaf(u0.y, r, x0.y + b0.y);
    o.z = fmaf(u1.x, r, x1.x + b1.x);
    o.w = fmaf(u1.y, r, x1.y + b1.y);
    ((float4*)out)[i] = o;
}

extern "C" void kernel_launch(void* const* d_in, const int* in_sizes, int n_in,
                              void* d_out, int out_size)
{
    const float* x      = (const float*)d_in[0];
    const int*   ei     = (const int*)d_in[1];
    const float* pseudo = (const float*)d_in[2];
    const float* W      = (const float*)d_in[3];
    const float* rootW  = (const float*)d_in[4];
    const float* attW   = (const float*)d_in[5];
    const float* bias   = (const float*)d_in[6];
    float* out = (float*)d_out;

    static bool attr_set = false;
    if (!attr_set) {
        cudaFuncSetAttribute(k2_mma,
            cudaFuncAttributeMaxDynamicSharedMemorySize, 61440);
        attr_set = true;
    }

    k0_tables<<<1, 32>>>(attW, bias);
    k1_conv<<<(NN + 255) / 256, 256>>>(x);
    k2_mma <<<NNP / 128, 256, 61440>>>(W, rootW);
    k3_edge<<<(NE * 8) / 256, 256>>>(ei, pseudo);
    k4_out <<<3125, 256>>>(out);
}